// round 12
// baseline (speedup 1.0000x reference)
#include <cuda_runtime.h>
#include <cuda_bf16.h>
#include <cstdint>

#define TLEN 32768
#define BATCH 4
#define NMEL 80
#define NBLK 16
#define TN 128
#define RSTRIDE (TLEN + 256)

// block kernel smem layout
#define SLOT_BYTES 61440
#define OFF_X_IN_SLOT 40960
#define X_HSTRIDE 8704
#define W_HSTRIDE 20480
#define W2_HSTRIDE 30720
#define OFF_XG 122880
#define XG_HSTRIDE 34816
#define SMEM_BLK 192512

// fused finals smem layout
#define OFF_XGF 81920
#define XGF_H 69632
#define SMEM_FIN 221184

typedef __nv_bfloat16 bf16;

// ---------------- device scratch ----------------
__device__ float g_resF[2][(size_t)BATCH*128*TLEN];
__device__ bf16  g_R[(size_t)8*BATCH*128*RSTRIDE];
__device__ bf16  g_cnd[2][(size_t)BATCH*96*TLEN];
__device__ float g_skip[(size_t)BATCH*256*TLEN];

__device__ bf16 g_Ws1[(size_t)NBLK*11*2*256*40];
__device__ bf16 g_W2 [(size_t)NBLK*4*2*384*40];
__device__ bf16 g_Wf [(size_t)2*8*2*256*40];
__device__ float g_Bg2[NBLK*2*128];
__device__ float g_Bs[NBLK*256];
__device__ float g_Br[NBLK*128];

#define RPLANE(pp,sh,pl) (g_R + ((((size_t)(pp)*2+(sh))*2+(pl)) * ((size_t)BATCH*128*RSTRIDE)))

// ---------------- helpers ----------------
__device__ __forceinline__ uint32_t smem_u32(const void* p) {
    uint32_t a;
    asm("{ .reg .u64 t; cvta.to.shared.u64 t, %1; cvt.u32.u64 %0, t; }" : "=r"(a) : "l"(p));
    return a;
}
__device__ __forceinline__ void cpa16(uint32_t dst, const void* src) {
    asm volatile("cp.async.cg.shared.global [%0], [%1], 16;" :: "r"(dst), "l"(src));
}
#define CP_COMMIT() asm volatile("cp.async.commit_group;" ::: "memory")
#define CP_WAIT1()  asm volatile("cp.async.wait_group 1;" ::: "memory")
__device__ __forceinline__ void mma16816(float* d, const uint32_t* a, const uint32_t* b) {
    asm volatile("mma.sync.aligned.m16n8k16.row.col.f32.bf16.bf16.f32 "
        "{%0,%1,%2,%3}, {%4,%5,%6,%7}, {%8,%9}, {%0,%1,%2,%3};"
        : "+f"(d[0]), "+f"(d[1]), "+f"(d[2]), "+f"(d[3])
        : "r"(a[0]), "r"(a[1]), "r"(a[2]), "r"(a[3]), "r"(b[0]), "r"(b[1]));
}
__device__ __forceinline__ void ldsm4(uint32_t* r, uint32_t addr) {
    asm volatile("ldmatrix.sync.aligned.m8n8.x4.shared.b16 {%0,%1,%2,%3}, [%4];"
        : "=r"(r[0]), "=r"(r[1]), "=r"(r[2]), "=r"(r[3]) : "r"(addr));
}
__device__ __forceinline__ void ldsm4t(uint32_t* r, uint32_t addr) {
    asm volatile("ldmatrix.sync.aligned.m8n8.x4.trans.shared.b16 {%0,%1,%2,%3}, [%4];"
        : "=r"(r[0]), "=r"(r[1]), "=r"(r[2]), "=r"(r[3]) : "r"(addr));
}

template<int MT>
__device__ __forceinline__ void mma_chunk(float (*acc)[8][4],
    uint32_t uWh, uint32_t uWl, uint32_t uXh, uint32_t uXl,
    int rbase, int cbase, int lane)
{
    int lt = lane >> 3, lr = lane & 7;
    #pragma unroll
    for (int ks = 0; ks < 2; ks++) {
        uint32_t aH[MT][4], aL[MT][4];
        #pragma unroll
        for (int mt = 0; mt < MT; mt++) {
            uint32_t off = ((uint32_t)(rbase + mt*16 + (lt & 1)*8 + lr) * 40
                            + ks*16 + (lt >> 1)*8) * 2;
            ldsm4(aH[mt], uWh + off);
            ldsm4(aL[mt], uWl + off);
        }
        uint32_t krow = ks*16 + (lt & 1)*8 + lr;
        #pragma unroll
        for (int np = 0; np < 4; np++) {
            uint32_t boff = (krow*136 + (uint32_t)(cbase + np*16 + (lt >> 1)*8)) * 2;
            uint32_t bH[4], bL[4];
            ldsm4t(bH, uXh + boff);
            ldsm4t(bL, uXl + boff);
            #pragma unroll
            for (int mt = 0; mt < MT; mt++) {
                #pragma unroll
                for (int nh = 0; nh < 2; nh++) {
                    mma16816(acc[mt][np*2+nh], aH[mt], &bH[nh*2]);
                    mma16816(acc[mt][np*2+nh], aL[mt], &bH[nh*2]);
                    mma16816(acc[mt][np*2+nh], aH[mt], &bL[nh*2]);
                }
            }
        }
    }
}

// ---------------- unified pack kernel ----------------
#define N1 ((size_t)NBLK*11*2*256*40)
#define N2 ((size_t)NBLK*4*2*384*40)
#define N3 ((size_t)2*8*2*256*40)
#define N4 ((size_t)NBLK*640)

__global__ void pack_all(const float* __restrict__ dil_w, const float* __restrict__ cond_w,
                         const float* __restrict__ skip_w, const float* __restrict__ res_w,
                         const float* __restrict__ out_w, const float* __restrict__ end_w,
                         const float* __restrict__ dil_b, const float* __restrict__ cond_b,
                         const float* __restrict__ skip_b, const float* __restrict__ res_b) {
    size_t idx = (size_t)blockIdx.x * 256 + threadIdx.x;
    if (idx < N1) {
        int kk = idx % 40;
        int m  = (idx / 40) % 256;
        int h  = (idx / (40*256)) % 2;
        int c  = (idx / (40*256*2)) % 11;
        int i  = idx / (40*256*2*11);
        float w = 0.f;
        if (kk < 32) {
            int k = c*32 + kk;
            int o = (m < 128) ? m : (120 + (m - 128));
            bool ov = (m < 128) ? (m < 120) : (m - 128 < 120);
            if (ov) {
                if (k < 128)      { if (k < 120) w = dil_w[((i*240+o)*120 + k)*2 + 0]; }
                else if (k < 256) { int q = k - 128; if (q < 120) w = dil_w[((i*240+o)*120 + q)*2 + 1]; }
                else if (k < 336) { int q = k - 256; if (q < NMEL) w = cond_w[(i*240+o)*80 + q]; }
            }
        }
        bf16 hi = __float2bfloat16_rn(w);
        g_Ws1[idx] = h ? __float2bfloat16_rn(w - __bfloat162float(hi)) : hi;
    } else if (idx < N1 + N2) {
        size_t rem = idx - N1;
        int kk = rem % 40;
        int m  = (rem / 40) % 384;
        int h  = (rem / (40*384)) % 2;
        int c  = (rem / (40*384*2)) % 4;
        int i  = rem / (40*384*2*4);
        float w = 0.f;
        if (kk < 32) {
            int k = c*32 + kk;
            if (k < 120) {
                if (m < 256) { if (m < 240) w = skip_w[(i*240+m)*120 + k]; }
                else         { int r = m - 256; if (r < 120) w = res_w[(i*120+r)*120 + k]; }
            }
        }
        bf16 hi = __float2bfloat16_rn(w);
        g_W2[rem] = h ? __float2bfloat16_rn(w - __bfloat162float(hi)) : hi;
    } else if (idx < N1 + N2 + N3) {
        size_t rem = idx - N1 - N2;
        int kk = rem % 40;
        int m  = (rem / 40) % 256;
        int h  = (rem / (40*256)) % 2;
        int c  = (rem / (40*256*2)) % 8;
        int ws = rem / (40*256*2*8);
        float w = 0.f;
        if (kk < 32) {
            int k = c*32 + kk;
            if (ws == 0) { if (k < 240) w = out_w[m*240 + k]; }
            else         { w = end_w[m*256 + k]; }
        }
        bf16 hi = __float2bfloat16_rn(w);
        g_Wf[rem] = h ? __float2bfloat16_rn(w - __bfloat162float(hi)) : hi;
    } else if (idx < N1 + N2 + N3 + N4) {
        int rem = (int)(idx - N1 - N2 - N3);
        int j = rem % 640, i = rem / 640;
        if (j < 256) {
            int h = j >> 7, m = j & 127;
            int o = h ? (120 + m) : m;
            g_Bg2[(i*2+h)*128 + m] = (m < 120) ? (dil_b[i*240+o] + cond_b[i*240+o]) : 0.f;
        } else if (j < 512) {
            int o = j - 256;
            g_Bs[i*256 + o] = (o < 240) ? skip_b[i*240+o] : 0.f;
        } else {
            int m = j - 512;
            g_Br[i*128 + m] = (m < 120) ? res_b[i*120+m] : 0.f;
        }
    }
}

__global__ void init_resA(const float* __restrict__ wav, const float* __restrict__ wav_w,
                          const float* __restrict__ wav_b) {
    size_t idx = (size_t)blockIdx.x * 256 + threadIdx.x;
    if (idx >= (size_t)BATCH*128*TLEN) return;
    int t = idx % TLEN;
    int r = (idx / TLEN) & 127;
    int b = idx / ((size_t)TLEN * 128);
    float v = (r < 120) ? (wav_w[r] * wav[(size_t)b*TLEN + t] + wav_b[r]) : 0.f;
    g_resF[0][idx] = v;
    bf16 h = __float2bfloat16_rn(v);
    bf16 l = __float2bfloat16_rn(v - __bfloat162float(h));
    size_t base = (size_t)(b*128 + r)*RSTRIDE;
    RPLANE(0,0,0)[base + 128 + t] = h;
    RPLANE(0,0,1)[base + 128 + t] = l;
    RPLANE(0,1,0)[base + 129 + t] = h;
    RPLANE(0,1,1)[base + 129 + t] = l;
    if (t == 0) {
        RPLANE(0,1,0)[base + 128] = __float2bfloat16_rn(0.f);
        RPLANE(0,1,1)[base + 128] = __float2bfloat16_rn(0.f);
    }
}
__global__ void init_cnd(const float* __restrict__ cond) {
    size_t idx = (size_t)blockIdx.x * 256 + threadIdx.x;
    if (idx >= (size_t)BATCH*96*TLEN) return;
    int t = idx % TLEN;
    int q = (idx / TLEN) % 96;
    int b = idx / ((size_t)TLEN * 96);
    float v = (q < NMEL) ? cond[((size_t)b*NMEL + q)*TLEN + t] : 0.f;
    bf16 h = __float2bfloat16_rn(v);
    g_cnd[0][idx] = h;
    g_cnd[1][idx] = __float2bfloat16_rn(v - __bfloat162float(h));
}

// ---------------- fused WaveNet block ----------------
__global__ __launch_bounds__(512, 1)
void block_mma(int blk, int dnext, int p, int first, int last) {
    extern __shared__ char smr[];
    uint32_t uS = smem_u32(smr);
    int tid = threadIdx.x, w = tid >> 5, lane = tid & 31;
    int mw = w >> 1, nw = w & 1;
    int rbase = mw * 32, cbase = nw * 64;
    int b = blockIdx.y, t0 = blockIdx.x * TN;

    float acc[3][8][4];
    #pragma unroll
    for (int x = 0; x < 2; x++)
        #pragma unroll
        for (int y = 0; y < 8; y++)
            #pragma unroll
            for (int q = 0; q < 4; q++) acc[x][y][q] = 0.f;

    // -------- stage-1: gate GEMM (M=256, K=352, 11 chunks) --------
    auto pf1 = [&](int c, int s) {
        uint32_t uSlot = uS + s*SLOT_BYTES;
        const char* ws = (const char*)g_Ws1 + (size_t)(blk*11 + c)*40960;
        #pragma unroll
        for (int q = 0; q < 5; q++) {
            int e = tid + q*512;
            cpa16(uSlot + e*16, ws + (size_t)e*16);
        }
        int row = tid >> 4, seg = tid & 15;
        uint32_t xd = uSlot + OFF_X_IN_SLOT + row*272 + seg*16;
        const char *sH, *sL;
        if (c < 8) {
            int sh = (c < 4) ? 1 : 0;
            int ch = (c & 3)*32 + row;
            size_t off = ((size_t)(b*128 + ch)*RSTRIDE + 128 + t0)*2 + seg*16;
            sH = (const char*)RPLANE(p, sh, 0) + off;
            sL = (const char*)RPLANE(p, sh, 1) + off;
        } else {
            int q2 = (c - 8)*32 + row;
            size_t off = ((size_t)(b*96 + q2)*TLEN + t0)*2 + seg*16;
            sH = (const char*)g_cnd[0] + off;
            sL = (const char*)g_cnd[1] + off;
        }
        cpa16(xd, sH);
        cpa16(xd + X_HSTRIDE, sL);
    };

    pf1(0, 0); CP_COMMIT();
    pf1(1, 1); CP_COMMIT();
    #pragma unroll 1
    for (int c = 0; c < 11; c++) {
        int s = c & 1;
        CP_WAIT1(); __syncthreads();
        uint32_t uW = uS + s*SLOT_BYTES;
        uint32_t uX = uW + OFF_X_IN_SLOT;
        mma_chunk<2>(acc, uW, uW + W_HSTRIDE, uX, uX + X_HSTRIDE, rbase, cbase, lane);
        __syncthreads();
        if (c + 2 < 11) pf1(c + 2, s);
        CP_COMMIT();
    }

    // -------- gate exchange + gating --------
    float* sGsF = (float*)smr;
    if (w >= 8) {
        int rb = (mw - 4) * 32;
        #pragma unroll
        for (int mt = 0; mt < 2; mt++)
            #pragma unroll
            for (int np = 0; np < 8; np++)
                #pragma unroll
                for (int hh = 0; hh < 2; hh++) {
                    int r = rb + mt*16 + (lane >> 2) + hh*8;
                    int cc = cbase + np*8 + (lane & 3)*2;
                    sGsF[r*132 + cc]     = acc[mt][np][hh*2+0];
                    sGsF[r*132 + cc + 1] = acc[mt][np][hh*2+1];
                }
    }
    __syncthreads();
    if (w < 8) {
        #pragma unroll
        for (int mt = 0; mt < 2; mt++)
            #pragma unroll
            for (int hh = 0; hh < 2; hh++) {
                int r = rbase + mt*16 + (lane >> 2) + hh*8;
                float bT = g_Bg2[(blk*2+0)*128 + r];
                float bS = g_Bg2[(blk*2+1)*128 + r];
                #pragma unroll
                for (int np = 0; np < 8; np++)
                    #pragma unroll
                    for (int e = 0; e < 2; e++) {
                        int cc = cbase + np*8 + (lane & 3)*2 + e;
                        float a = acc[mt][np][hh*2+e] + bT;
                        float g = sGsF[r*132 + cc] + bS;
                        float th = 1.f - __fdividef(2.f, __expf(2.f*a) + 1.f);
                        float sg = __fdividef(1.f, 1.f + __expf(-g));
                        float v = th * sg;
                        bf16 hv = __float2bfloat16_rn(v);
                        *(bf16*)(smr + OFF_XG + (r*136 + cc)*2) = hv;
                        *(bf16*)(smr + OFF_XG + XG_HSTRIDE + (r*136 + cc)*2) =
                            __float2bfloat16_rn(v - __bfloat162float(hv));
                    }
            }
    }
    __syncthreads();

    // -------- stage 2: merged skip(256)+res(128) GEMM, M=384, K=128 --------
    #pragma unroll
    for (int x = 0; x < 3; x++)
        #pragma unroll
        for (int y = 0; y < 8; y++)
            #pragma unroll
            for (int q = 0; q < 4; q++) acc[x][y][q] = 0.f;

    auto pf2 = [&](int c, int s) {
        const char* ws = (const char*)g_W2 + (size_t)(blk*4 + c)*61440;
        uint32_t uSlot = uS + s*SLOT_BYTES;
        #pragma unroll
        for (int q = 0; q < 8; q++) {
            int e = tid + q*512;
            if (e < 3840) cpa16(uSlot + e*16, ws + (size_t)e*16);
        }
    };
    pf2(0, 0); CP_COMMIT();
    pf2(1, 1); CP_COMMIT();
    int rb3 = mw * 48;
    #pragma unroll 1
    for (int c = 0; c < 4; c++) {
        int s = c & 1;
        CP_WAIT1(); __syncthreads();
        uint32_t uW = uS + s*SLOT_BYTES;
        uint32_t uXG = uS + OFF_XG + c*8704;
        mma_chunk<3>(acc, uW, uW + W2_HSTRIDE, uXG, uXG + XG_HSTRIDE, rb3, cbase, lane);
        __syncthreads();
        if (c + 2 < 4) pf2(c + 2, s);
        CP_COMMIT();
    }

    // -------- merged epilogue: stg[384][68] --------
    {
        float* stg = (float*)smr;
        #pragma unroll 1
        for (int p2 = 0; p2 < 2; p2++) {
            if (nw == p2) {
                #pragma unroll
                for (int mt = 0; mt < 3; mt++)
                    #pragma unroll
                    for (int np = 0; np < 8; np++)
                        #pragma unroll
                        for (int hh = 0; hh < 2; hh++) {
                            int r = rb3 + mt*16 + (lane >> 2) + hh*8;
                            int cc = np*8 + (lane & 3)*2;
                            stg[r*68 + cc]     = acc[mt][np][hh*2+0];
                            stg[r*68 + cc + 1] = acc[mt][np][hh*2+1];
                        }
            }
            __syncthreads();
            {   // skip rows 0..255
                int r = tid >> 1, half = tid & 1;
                float bias = g_Bs[blk*256 + r];
                float* dst = g_skip + ((size_t)b*256 + r)*TLEN + t0 + p2*64 + half*32;
                const float* st = stg + r*68 + half*32;
                #pragma unroll
                for (int j = 0; j < 8; j++) {
                    float4 v = *(const float4*)(st + j*4);
                    v.x += bias; v.y += bias; v.z += bias; v.w += bias;
                    if (!first) {
                        float4 o = *(const float4*)(dst + j*4);
                        v.x += o.x; v.y += o.y; v.z += o.z; v.w += o.w;
                    }
                    *(float4*)(dst + j*4) = v;
                }
            }
            {   // residual rows 256..383
                int r = tid >> 2, qd = tid & 3;
                int ct = t0 + p2*64 + qd*16;
                float bias = g_Br[blk*128 + r];
                size_t fidx = (size_t)(b*128 + r)*TLEN + ct;
                const float* oldp = g_resF[p] + fidx;
                float* newp = g_resF[1-p] + fidx;
                const float* st = stg + (256 + r)*68 + qd*16;
                __align__(16) float v[16];
                #pragma unroll
                for (int j = 0; j < 4; j++) {
                    float4 sv = *(const float4*)(st + j*4);
                    float4 ov = *(const float4*)(oldp + j*4);
                    v[j*4+0] = sv.x + bias + ov.x;
                    v[j*4+1] = sv.y + bias + ov.y;
                    v[j*4+2] = sv.z + bias + ov.z;
                    v[j*4+3] = sv.w + bias + ov.w;
                    *(float4*)(newp + j*4) = make_float4(v[j*4+0], v[j*4+1], v[j*4+2], v[j*4+3]);
                }
                __align__(16) bf16 hv[16], lv[16];
                #pragma unroll
                for (int j = 0; j < 16; j++) {
                    hv[j] = __float2bfloat16_rn(v[j]);
                    lv[j] = __float2bfloat16_rn(v[j] - __bfloat162float(hv[j]));
                }
                size_t rb_ = (size_t)(b*128 + r)*RSTRIDE + 128 + ct;
                bf16* dH = RPLANE(1-p,0,0) + rb_;
                bf16* dL = RPLANE(1-p,0,1) + rb_;
                ((uint4*)dH)[0] = ((uint4*)hv)[0]; ((uint4*)dH)[1] = ((uint4*)hv)[1];
                ((uint4*)dL)[0] = ((uint4*)lv)[0]; ((uint4*)dL)[1] = ((uint4*)lv)[1];
                if (!last) {
                    bf16* sH = RPLANE(1-p,1,0) + rb_ + dnext;
                    bf16* sL = RPLANE(1-p,1,1) + rb_ + dnext;
                    if ((dnext & 7) == 0) {
                        ((uint4*)sH)[0] = ((uint4*)hv)[0]; ((uint4*)sH)[1] = ((uint4*)hv)[1];
                        ((uint4*)sL)[0] = ((uint4*)lv)[0]; ((uint4*)sL)[1] = ((uint4*)lv)[1];
                    } else {
                        #pragma unroll
                        for (int j = 0; j < 16; j++) { sH[j] = hv[j]; sL[j] = lv[j]; }
                    }
                }
            }
            __syncthreads();
        }
        if (t0 == 0 && !last) {
            bf16 z = __float2bfloat16_rn(0.f);
            for (int e = tid; e < 128*dnext; e += 512) {
                int r = e / dnext, cc = e - r*dnext;
                size_t ix = (size_t)(b*128 + r)*RSTRIDE + 128 + cc;
                RPLANE(1-p,1,0)[ix] = z;
                RPLANE(1-p,1,1)[ix] = z;
            }
        }
    }
}

// ---------------- fused finals: out then end (per-tile, no global round-trip) ----
__global__ __launch_bounds__(512, 1)
void final_fused(const float* __restrict__ out_b, const float* __restrict__ end_b,
                 float* __restrict__ dst) {
    extern __shared__ char smr[];
    uint32_t uS = smem_u32(smr);
    int tid = threadIdx.x, w = tid >> 5, lane = tid & 31;
    int mw = w >> 1, nw = w & 1;
    int rbase = mw * 32, cbase = nw * 64;
    int b = blockIdx.y, t0 = blockIdx.x * TN;

    float acc[2][8][4];
    #pragma unroll
    for (int x = 0; x < 2; x++)
        #pragma unroll
        for (int y = 0; y < 8; y++)
            #pragma unroll
            for (int q = 0; q < 4; q++) acc[x][y][q] = 0.f;

    // ---- stage A: out = out_w @ relu(skip) ----
    auto pfA = [&](int c, int s) {
        uint32_t uSlot = uS + s*40960;
        const char* ws = (const char*)g_Wf + (size_t)c*40960;
        #pragma unroll
        for (int q = 0; q < 5; q++) {
            int e = tid + q*512;
            cpa16(uSlot + e*16, ws + (size_t)e*16);
        }
        #pragma unroll
        for (int q = 0; q < 2; q++) {
            int e = tid + q*512;
            int row = e >> 5, seg = e & 31;
            size_t off = ((size_t)(b*256 + c*32 + row)*TLEN + t0)*4 + seg*16;
            cpa16(uS + OFF_XGF + s*16384 + row*512 + seg*16, (const char*)g_skip + off);
        }
    };

    pfA(0, 0); CP_COMMIT();
    pfA(1, 1); CP_COMMIT();
    #pragma unroll 1
    for (int c = 0; c < 8; c++) {
        int s = c & 1;
        CP_WAIT1(); __syncthreads();
        float* raw = (float*)(smr + OFF_XGF + s*16384);
        char* xsp = smr + OFF_XGF + 32768 + s*17408;
        bf16* Xh = (bf16*)xsp;
        bf16* Xl = (bf16*)(xsp + 8704);
        #pragma unroll
        for (int i2 = 0; i2 < 8; i2++) {
            int e = tid + i2*512;
            int t = e & 127, k = e >> 7;
            float v = fmaxf(raw[k*128 + t], 0.f);
            bf16 hv = __float2bfloat16_rn(v);
            Xh[k*136 + t] = hv;
            Xl[k*136 + t] = __float2bfloat16_rn(v - __bfloat162float(hv));
        }
        __syncthreads();
        uint32_t uW = uS + s*40960;
        uint32_t uX = uS + OFF_XGF + 32768 + s*17408;
        mma_chunk<2>(acc, uW, uW + W_HSTRIDE, uX, uX + 8704, rbase, cbase, lane);
        __syncthreads();
        if (c + 2 < 8) pfA(c + 2, s);
        CP_COMMIT();
    }

    // ---- relu(out + bias) -> split bf16 planes in XGF ----
    #pragma unroll
    for (int mt = 0; mt < 2; mt++)
        #pragma unroll
        for (int hh = 0; hh < 2; hh++) {
            int r = rbase + mt*16 + (lane >> 2) + hh*8;
            float bi = out_b[r];
            #pragma unroll
            for (int np = 0; np < 8; np++)
                #pragma unroll
                for (int e = 0; e < 2; e++) {
                    int cc = cbase + np*8 + (lane & 3)*2 + e;
                    float v = fmaxf(acc[mt][np][hh*2+e] + bi, 0.f);
                    bf16 hv = __float2bfloat16_rn(v);
                    size_t off = (size_t)(r >> 5)*8704 + (r & 31)*272 + cc*2;
                    *(bf16*)(smr + OFF_XGF + off) = hv;
                    *(bf16*)(smr + OFF_XGF + XGF_H + off) =
                        __float2bfloat16_rn(v - __bfloat162float(hv));
                }
        }
    __syncthreads();

    // ---- stage B: end = end_w @ relu(out), X already in smem ----
    #pragma unroll
    for (int x = 0; x < 2; x++)
        #pragma unroll
        for (int y = 0; y < 8; y++)
            #pragma unroll
            for (int q = 0; q < 4; q++) acc[x][y][q] = 0.f;

    auto pfB = [&](int c, int s) {
        uint32_t uSlot = uS + s*40960;
        const char* ws = (const char*)g_Wf + (size_t)(8 + c)*40960;
        #pragma unroll
        for (int q = 0; q < 5; q++) {
            int e = tid + q*512;
            cpa16(uSlot + e*16, ws + (size_t)e*16);
        }
    };
    pfB(0, 0); CP_COMMIT();
    pfB(1, 1); CP_COMMIT();
    #pragma unroll 1
    for (int c = 0; c < 8; c++) {
        int s = c & 1;
        CP_WAIT1(); __syncthreads();
        uint32_t uW = uS + s*40960;
        uint32_t uX = uS + OFF_XGF + c*8704;
        mma_chunk<2>(acc, uW, uW + W_HSTRIDE, uX, uX + XGF_H, rbase, cbase, lane);
        __syncthreads();
        if (c + 2 < 8) pfB(c + 2, s);
        CP_COMMIT();
    }

    float* stg = (float*)smr;
    #pragma unroll 1
    for (int p2 = 0; p2 < 2; p2++) {
        if (nw == p2) {
            #pragma unroll
            for (int mt = 0; mt < 2; mt++)
                #pragma unroll
                for (int np = 0; np < 8; np++)
                    #pragma unroll
                    for (int hh = 0; hh < 2; hh++) {
                        int r = rbase + mt*16 + (lane >> 2) + hh*8;
                        int cc = np*8 + (lane & 3)*2;
                        stg[r*68 + cc]     = acc[mt][np][hh*2+0];
                        stg[r*68 + cc + 1] = acc[mt][np][hh*2+1];
                    }
        }
        __syncthreads();
        {
            int r = tid >> 1, half = tid & 1;
            float bi = end_b[r];
            float* dp = dst + ((size_t)b*256 + r)*TLEN + t0 + p2*64 + half*32;
            const float* st = stg + r*68 + half*32;
            #pragma unroll
            for (int j = 0; j < 8; j++) {
                float4 v = *(const float4*)(st + j*4);
                v.x += bi; v.y += bi; v.z += bi; v.w += bi;
                *(float4*)(dp + j*4) = v;
            }
        }
        __syncthreads();
    }
}

// ---------------- launch ----------------
extern "C" void kernel_launch(void* const* d_in, const int* in_sizes, int n_in,
                              void* d_out, int out_size) {
    const float* wav    = (const float*)d_in[0];
    const float* cond   = (const float*)d_in[1];
    const float* wav_w  = (const float*)d_in[2];
    const float* wav_b  = (const float*)d_in[3];
    const float* cond_w = (const float*)d_in[4];
    const float* cond_b = (const float*)d_in[5];
    const float* dil_w  = (const float*)d_in[6];
    const float* dil_b  = (const float*)d_in[7];
    const float* skip_w = (const float*)d_in[8];
    const float* skip_b = (const float*)d_in[9];
    const float* res_w  = (const float*)d_in[10];
    const float* res_b  = (const float*)d_in[11];
    const float* out_w  = (const float*)d_in[12];
    const float* out_b  = (const float*)d_in[13];
    const float* end_w  = (const float*)d_in[14];
    const float* end_b  = (const float*)d_in[15];

    cudaFuncSetAttribute(block_mma, cudaFuncAttributeMaxDynamicSharedMemorySize, SMEM_BLK);
    cudaFuncSetAttribute(final_fused, cudaFuncAttributeMaxDynamicSharedMemorySize, SMEM_FIN);

    size_t ntot = N1 + N2 + N3 + N4;
    pack_all<<<(int)((ntot + 255)/256), 256>>>(dil_w, cond_w, skip_w, res_w, out_w, end_w,
                                               dil_b, cond_b, skip_b, res_b);
    init_resA<<<(int)(((size_t)BATCH*128*TLEN + 255)/256), 256>>>(wav, wav_w, wav_b);
    init_cnd<<<(int)(((size_t)BATCH*96*TLEN + 255)/256), 256>>>(cond);

    dim3 grid(TLEN / TN, BATCH);
    for (int i = 0; i < NBLK; i++) {
        int dnext = 1 << ((i + 1) % 8);
        block_mma<<<grid, 512, SMEM_BLK>>>(i, dnext, i & 1, (i == 0) ? 1 : 0, (i == NBLK-1) ? 1 : 0);
    }
    final_fused<<<grid, 512, SMEM_FIN>>>(out_b, end_b, (float*)d_out);
}

// round 17
// speedup vs baseline: 1.1195x; 1.1195x over previous
#include <cuda_runtime.h>
#include <cuda_bf16.h>
#include <cstdint>

#define TLEN 32768
#define BATCH 4
#define NMEL 80
#define NBLK 16
#define TN 64
#define RSTRIDE (TLEN + 256)

// ---- block kernel smem regions (bytes) ----
#define BW_OFF   0
#define BX_OFF   40960
#define BXG_OFF  59392
#define BXG_H    18432
#define SMEM_BLK 96256

// ---- finals (R9 layout, TN=128) ----
#define FSLOT 74752
#define F_OFF_X 40960
#define F_XH 8704
#define F_OFF_RAW 58368
#define SMEM_FIN 149504
#define W_HSTRIDE 20480

typedef __nv_bfloat16 bf16;

// ---------------- device scratch ----------------
__device__ float g_resF[2][(size_t)BATCH*128*TLEN];
__device__ bf16  g_R[(size_t)8*BATCH*128*RSTRIDE];
__device__ bf16  g_cnd[2][(size_t)BATCH*96*TLEN];
__device__ float g_skip[(size_t)BATCH*256*TLEN];
__device__ float g_obuf[(size_t)BATCH*256*TLEN];

__device__ bf16 g_Ws1[(size_t)NBLK*11*2*256*40];
__device__ bf16 g_W2s[(size_t)NBLK*4*2*256*40];
__device__ bf16 g_W2r[(size_t)NBLK*4*2*128*40];
__device__ bf16 g_Wf [(size_t)2*8*2*256*40];
__device__ float g_Bg2[NBLK*2*128];
__device__ float g_Bs[NBLK*256];
__device__ float g_Br[NBLK*128];

#define RPLANE(pp,sh,pl) (g_R + ((((size_t)(pp)*2+(sh))*2+(pl)) * ((size_t)BATCH*128*RSTRIDE)))

// ---------------- helpers ----------------
__device__ __forceinline__ uint32_t smem_u32(const void* p) {
    uint32_t a;
    asm("{ .reg .u64 t; cvta.to.shared.u64 t, %1; cvt.u32.u64 %0, t; }" : "=r"(a) : "l"(p));
    return a;
}
__device__ __forceinline__ void cpa16(uint32_t dst, const void* src) {
    asm volatile("cp.async.cg.shared.global [%0], [%1], 16;" :: "r"(dst), "l"(src));
}
#define CP_COMMIT() asm volatile("cp.async.commit_group;" ::: "memory")
#define CP_WAIT0()  asm volatile("cp.async.wait_group 0;" ::: "memory")
#define CP_WAIT1()  asm volatile("cp.async.wait_group 1;" ::: "memory")
__device__ __forceinline__ void mma16816(float* d, const uint32_t* a, const uint32_t* b) {
    asm volatile("mma.sync.aligned.m16n8k16.row.col.f32.bf16.bf16.f32 "
        "{%0,%1,%2,%3}, {%4,%5,%6,%7}, {%8,%9}, {%0,%1,%2,%3};"
        : "+f"(d[0]), "+f"(d[1]), "+f"(d[2]), "+f"(d[3])
        : "r"(a[0]), "r"(a[1]), "r"(a[2]), "r"(a[3]), "r"(b[0]), "r"(b[1]));
}
__device__ __forceinline__ void ldsm4(uint32_t* r, uint32_t addr) {
    asm volatile("ldmatrix.sync.aligned.m8n8.x4.shared.b16 {%0,%1,%2,%3}, [%4];"
        : "=r"(r[0]), "=r"(r[1]), "=r"(r[2]), "=r"(r[3]) : "r"(addr));
}
__device__ __forceinline__ void ldsm4t(uint32_t* r, uint32_t addr) {
    asm volatile("ldmatrix.sync.aligned.m8n8.x4.trans.shared.b16 {%0,%1,%2,%3}, [%4];"
        : "=r"(r[0]), "=r"(r[1]), "=r"(r[2]), "=r"(r[3]) : "r"(addr));
}

// generic triple-product chunk: W rows [m][40] bf16, X rows [k][XSTR bytes]
template<int MT, int NP, int XSTR>
__device__ __forceinline__ void mma_chunkT(float (*acc)[NP*2][4],
    uint32_t uWh, uint32_t uWl, uint32_t uXh, uint32_t uXl,
    int rbase, int cbase, int lane)
{
    int lt = lane >> 3, lr = lane & 7;
    #pragma unroll
    for (int ks = 0; ks < 2; ks++) {
        uint32_t aH[MT][4], aL[MT][4];
        #pragma unroll
        for (int mt = 0; mt < MT; mt++) {
            uint32_t off = ((uint32_t)(rbase + mt*16 + (lt & 1)*8 + lr) * 40
                            + ks*16 + (lt >> 1)*8) * 2;
            ldsm4(aH[mt], uWh + off);
            ldsm4(aL[mt], uWl + off);
        }
        uint32_t krow = ks*16 + (lt & 1)*8 + lr;
        #pragma unroll
        for (int np = 0; np < NP; np++) {
            uint32_t boff = krow*XSTR + (uint32_t)(cbase + np*16 + (lt >> 1)*8) * 2;
            uint32_t bH[4], bL[4];
            ldsm4t(bH, uXh + boff);
            ldsm4t(bL, uXl + boff);
            #pragma unroll
            for (int mt = 0; mt < MT; mt++) {
                #pragma unroll
                for (int nh = 0; nh < 2; nh++) {
                    mma16816(acc[mt][np*2+nh], aH[mt], &bH[nh*2]);
                    mma16816(acc[mt][np*2+nh], aL[mt], &bH[nh*2]);
                    mma16816(acc[mt][np*2+nh], aH[mt], &bL[nh*2]);
                }
            }
        }
    }
}

// ---------------- unified pack kernel ----------------
#define N1 ((size_t)NBLK*11*2*256*40)
#define N2 ((size_t)NBLK*4*2*384*40)
#define N3 ((size_t)2*8*2*256*40)
#define N4 ((size_t)NBLK*640)

__global__ void pack_all(const float* __restrict__ dil_w, const float* __restrict__ cond_w,
                         const float* __restrict__ skip_w, const float* __restrict__ res_w,
                         const float* __restrict__ out_w, const float* __restrict__ end_w,
                         const float* __restrict__ dil_b, const float* __restrict__ cond_b,
                         const float* __restrict__ skip_b, const float* __restrict__ res_b) {
    size_t idx = (size_t)blockIdx.x * 256 + threadIdx.x;
    if (idx < N1) {
        int kk = idx % 40;
        int m  = (idx / 40) % 256;
        int h  = (idx / (40*256)) % 2;
        int c  = (idx / (40*256*2)) % 11;
        int i  = idx / (40*256*2*11);
        float w = 0.f;
        if (kk < 32) {
            int k = c*32 + kk;
            int o = (m < 128) ? m : (120 + (m - 128));
            bool ov = (m < 128) ? (m < 120) : (m - 128 < 120);
            if (ov) {
                if (k < 128)      { if (k < 120) w = dil_w[((i*240+o)*120 + k)*2 + 0]; }
                else if (k < 256) { int q = k - 128; if (q < 120) w = dil_w[((i*240+o)*120 + q)*2 + 1]; }
                else if (k < 336) { int q = k - 256; if (q < NMEL) w = cond_w[(i*240+o)*80 + q]; }
            }
        }
        bf16 hi = __float2bfloat16_rn(w);
        g_Ws1[idx] = h ? __float2bfloat16_rn(w - __bfloat162float(hi)) : hi;
    } else if (idx < N1 + N2) {
        size_t rem = idx - N1;
        int kk = rem % 40;
        int m  = (rem / 40) % 384;
        int h  = (rem / (40*384)) % 2;
        int c  = (rem / (40*384*2)) % 4;
        int i  = rem / (40*384*2*4);
        float w = 0.f;
        if (kk < 32) {
            int k = c*32 + kk;
            if (k < 120) {
                if (m < 256) { if (m < 240) w = skip_w[(i*240+m)*120 + k]; }
                else         { int r = m - 256; if (r < 120) w = res_w[(i*120+r)*120 + k]; }
            }
        }
        bf16 hi = __float2bfloat16_rn(w);
        bf16 v = h ? __float2bfloat16_rn(w - __bfloat162float(hi)) : hi;
        if (m < 256) g_W2s[((((size_t)i*4+c)*2+h)*256 + m)*40 + kk] = v;
        else         g_W2r[((((size_t)i*4+c)*2+h)*128 + (m-256))*40 + kk] = v;
    } else if (idx < N1 + N2 + N3) {
        size_t rem = idx - N1 - N2;
        int kk = rem % 40;
        int m  = (rem / 40) % 256;
        int h  = (rem / (40*256)) % 2;
        int c  = (rem / (40*256*2)) % 8;
        int ws = rem / (40*256*2*8);
        float w = 0.f;
        if (kk < 32) {
            int k = c*32 + kk;
            if (ws == 0) { if (k < 240) w = out_w[m*240 + k]; }
            else         { w = end_w[m*256 + k]; }
        }
        bf16 hi = __float2bfloat16_rn(w);
        g_Wf[rem] = h ? __float2bfloat16_rn(w - __bfloat162float(hi)) : hi;
    } else if (idx < N1 + N2 + N3 + N4) {
        int rem = (int)(idx - N1 - N2 - N3);
        int j = rem % 640, i = rem / 640;
        if (j < 256) {
            int h = j >> 7, m = j & 127;
            int o = h ? (120 + m) : m;
            g_Bg2[(i*2+h)*128 + m] = (m < 120) ? (dil_b[i*240+o] + cond_b[i*240+o]) : 0.f;
        } else if (j < 512) {
            int o = j - 256;
            g_Bs[i*256 + o] = (o < 240) ? skip_b[i*240+o] : 0.f;
        } else {
            int m = j - 512;
            g_Br[i*128 + m] = (m < 120) ? res_b[i*120+m] : 0.f;
        }
    }
}

__global__ void init_resA(const float* __restrict__ wav, const float* __restrict__ wav_w,
                          const float* __restrict__ wav_b) {
    size_t idx = (size_t)blockIdx.x * 256 + threadIdx.x;
    if (idx >= (size_t)BATCH*128*TLEN) return;
    int t = idx % TLEN;
    int r = (idx / TLEN) & 127;
    int b = idx / ((size_t)TLEN * 128);
    float v = (r < 120) ? (wav_w[r] * wav[(size_t)b*TLEN + t] + wav_b[r]) : 0.f;
    g_resF[0][idx] = v;
    bf16 h = __float2bfloat16_rn(v);
    bf16 l = __float2bfloat16_rn(v - __bfloat162float(h));
    size_t base = (size_t)(b*128 + r)*RSTRIDE;
    RPLANE(0,0,0)[base + 128 + t] = h;
    RPLANE(0,0,1)[base + 128 + t] = l;
    RPLANE(0,1,0)[base + 129 + t] = h;
    RPLANE(0,1,1)[base + 129 + t] = l;
    if (t == 0) {
        RPLANE(0,1,0)[base + 128] = __float2bfloat16_rn(0.f);
        RPLANE(0,1,1)[base + 128] = __float2bfloat16_rn(0.f);
    }
}
__global__ void init_cnd(const float* __restrict__ cond) {
    size_t idx = (size_t)blockIdx.x * 256 + threadIdx.x;
    if (idx >= (size_t)BATCH*96*TLEN) return;
    int t = idx % TLEN;
    int q = (idx / TLEN) % 96;
    int b = idx / ((size_t)TLEN * 96);
    float v = (q < NMEL) ? cond[((size_t)b*NMEL + q)*TLEN + t] : 0.f;
    bf16 h = __float2bfloat16_rn(v);
    g_cnd[0][idx] = h;
    g_cnd[1][idx] = __float2bfloat16_rn(v - __bfloat162float(h));
}

// ---------------- fused WaveNet block: TN=64, 256 thr, 2 CTA/SM ----------------
__global__ __launch_bounds__(256, 2)
void block_mma(int blk, int dnext, int p, int first, int last) {
    extern __shared__ char smr[];
    uint32_t uS = smem_u32(smr);
    int tid = threadIdx.x, w = tid >> 5, lane = tid & 31;
    int mw = w >> 1, nw = w & 1;
    int b = blockIdx.y, t0 = blockIdx.x * TN;

    float acc[4][4][4];
    #pragma unroll
    for (int x = 0; x < 4; x++)
        #pragma unroll
        for (int y = 0; y < 4; y++)
            #pragma unroll
            for (int q = 0; q < 4; q++) acc[x][y][q] = 0.f;

    // ---- loaders ----
    auto loadW1 = [&](int c) {
        const char* ws = (const char*)g_Ws1 + (size_t)(blk*11 + c)*40960;
        #pragma unroll
        for (int q = 0; q < 10; q++) {
            int e = tid + q*256;
            cpa16(uS + BW_OFF + e*16, ws + (size_t)e*16);
        }
    };
    auto loadX1 = [&](int c, int s) {
        int row = tid >> 3, seg = tid & 7;
        uint32_t xd = uS + BX_OFF + s*9216 + row*144 + seg*16;
        const char *sH, *sL;
        if (c < 8) {
            int sh = (c < 4) ? 1 : 0;
            int ch = (c & 3)*32 + row;
            size_t off = ((size_t)(b*128 + ch)*RSTRIDE + 128 + t0)*2 + seg*16;
            sH = (const char*)RPLANE(p, sh, 0) + off;
            sL = (const char*)RPLANE(p, sh, 1) + off;
        } else {
            int q2 = (c - 8)*32 + row;
            size_t off = ((size_t)(b*96 + q2)*TLEN + t0)*2 + seg*16;
            sH = (const char*)g_cnd[0] + off;
            sL = (const char*)g_cnd[1] + off;
        }
        cpa16(xd, sH);
        cpa16(xd + 4608, sL);
    };

    // ---- stage 1: gate GEMM, K=352 (11 chunks) ----
    loadX1(0, 0); CP_COMMIT();
    #pragma unroll 1
    for (int c = 0; c < 11; c++) {
        int s = c & 1;
        loadW1(c); CP_COMMIT();
        if (c < 10) { loadX1(c + 1, s ^ 1); CP_COMMIT(); }
        if (c < 10) { CP_WAIT1(); } else { CP_WAIT0(); }
        __syncthreads();
        uint32_t uX = uS + BX_OFF + s*9216;
        mma_chunkT<4,2,144>(acc, uS + BW_OFF, uS + BW_OFF + 20480,
                            uX, uX + 4608, mw*64, nw*32, lane);
        __syncthreads();
    }

    // ---- gate exchange + gating (CORRECT fragment indexing) ----
    float* sGsF = (float*)smr;   // [128][68], overlays W region
    if (w >= 4) {   // sigmoid half (stage-1 rows 128..255 -> gate rows 0..127)
        #pragma unroll
        for (int mt = 0; mt < 4; mt++)
            #pragma unroll
            for (int j = 0; j < 4; j++)
                #pragma unroll
                for (int hh = 0; hh < 2; hh++) {
                    int r = (mw - 2)*64 + mt*16 + (lane >> 2) + hh*8;
                    int cc = nw*32 + j*8 + (lane & 3)*2;
                    sGsF[r*68 + cc]     = acc[mt][j][hh*2+0];
                    sGsF[r*68 + cc + 1] = acc[mt][j][hh*2+1];
                }
    }
    __syncthreads();
    if (w < 4) {    // tanh half computes gate, writes XG planes
        #pragma unroll
        for (int mt = 0; mt < 4; mt++)
            #pragma unroll
            for (int hh = 0; hh < 2; hh++) {
                int r = mw*64 + mt*16 + (lane >> 2) + hh*8;
                float bT = g_Bg2[(blk*2+0)*128 + r];
                float bS = g_Bg2[(blk*2+1)*128 + r];
                #pragma unroll
                for (int j = 0; j < 4; j++)
                    #pragma unroll
                    for (int e = 0; e < 2; e++) {
                        int cc = nw*32 + j*8 + (lane & 3)*2 + e;
                        float a = acc[mt][j][hh*2+e] + bT;
                        float g = sGsF[r*68 + cc] + bS;
                        float th = 1.f - __fdividef(2.f, __expf(2.f*a) + 1.f);
                        float sg = __fdividef(1.f, 1.f + __expf(-g));
                        float v = th * sg;
                        bf16 hv = __float2bfloat16_rn(v);
                        *(bf16*)(smr + BXG_OFF + r*144 + cc*2) = hv;
                        *(bf16*)(smr + BXG_OFF + BXG_H + r*144 + cc*2) =
                            __float2bfloat16_rn(v - __bfloat162float(hv));
                    }
            }
    }
    __syncthreads();

    // ---- stage 2a: skip GEMM (M=256, K=128, 4 chunks) ----
    #pragma unroll
    for (int x = 0; x < 4; x++)
        #pragma unroll
        for (int y = 0; y < 4; y++)
            #pragma unroll
            for (int q = 0; q < 4; q++) acc[x][y][q] = 0.f;
    #pragma unroll 1
    for (int c = 0; c < 4; c++) {
        const char* ws = (const char*)g_W2s + (size_t)(blk*4 + c)*40960;
        #pragma unroll
        for (int q = 0; q < 10; q++) {
            int e = tid + q*256;
            cpa16(uS + BW_OFF + e*16, ws + (size_t)e*16);
        }
        CP_COMMIT(); CP_WAIT0();
        __syncthreads();
        uint32_t uXG = uS + BXG_OFF + c*32*144;
        mma_chunkT<4,2,144>(acc, uS + BW_OFF, uS + BW_OFF + 20480,
                            uXG, uXG + BXG_H, mw*64, nw*32, lane);
        __syncthreads();
    }
    // skip epilogue: stg[256][36] overlays W region
    {
        float* stg = (float*)smr;
        #pragma unroll 1
        for (int p2 = 0; p2 < 2; p2++) {
            if (nw == p2) {
                #pragma unroll
                for (int mt = 0; mt < 4; mt++)
                    #pragma unroll
                    for (int j = 0; j < 4; j++)
                        #pragma unroll
                        for (int hh = 0; hh < 2; hh++) {
                            int r = mw*64 + mt*16 + (lane >> 2) + hh*8;
                            int cc = j*8 + (lane & 3)*2;
                            stg[r*36 + cc]     = acc[mt][j][hh*2+0];
                            stg[r*36 + cc + 1] = acc[mt][j][hh*2+1];
                        }
            }
            __syncthreads();
            {
                int r = tid;
                float bias = g_Bs[blk*256 + r];
                float* dst = g_skip + ((size_t)b*256 + r)*TLEN + t0 + p2*32;
                const float* st = stg + r*36;
                #pragma unroll
                for (int j = 0; j < 8; j++) {
                    float4 v = *(const float4*)(st + j*4);
                    v.x += bias; v.y += bias; v.z += bias; v.w += bias;
                    if (!first) {
                        float4 o = *(const float4*)(dst + j*4);
                        v.x += o.x; v.y += o.y; v.z += o.z; v.w += o.w;
                    }
                    *(float4*)(dst + j*4) = v;
                }
            }
            __syncthreads();
        }
    }

    // ---- stage 2b: residual GEMM (M=128, K=128, 4 chunks) ----
    #pragma unroll
    for (int x = 0; x < 2; x++)
        #pragma unroll
        for (int y = 0; y < 4; y++)
            #pragma unroll
            for (int q = 0; q < 4; q++) acc[x][y][q] = 0.f;
    #pragma unroll 1
    for (int c = 0; c < 4; c++) {
        const char* ws = (const char*)g_W2r + (size_t)(blk*4 + c)*20480;
        #pragma unroll
        for (int q = 0; q < 5; q++) {
            int e = tid + q*256;
            cpa16(uS + BW_OFF + e*16, ws + (size_t)e*16);
        }
        CP_COMMIT(); CP_WAIT0();
        __syncthreads();
        uint32_t uXG = uS + BXG_OFF + c*32*144;
        mma_chunkT<2,2,144>(acc, uS + BW_OFF, uS + BW_OFF + 10240,
                            uXG, uXG + BXG_H, mw*32, nw*32, lane);
        __syncthreads();
    }
    // residual epilogue: stg[128][36]
    {
        float* stg = (float*)smr;
        #pragma unroll 1
        for (int p2 = 0; p2 < 2; p2++) {
            if (nw == p2) {
                #pragma unroll
                for (int mt = 0; mt < 2; mt++)
                    #pragma unroll
                    for (int j = 0; j < 4; j++)
                        #pragma unroll
                        for (int hh = 0; hh < 2; hh++) {
                            int r = mw*32 + mt*16 + (lane >> 2) + hh*8;
                            int cc = j*8 + (lane & 3)*2;
                            stg[r*36 + cc]     = acc[mt][j][hh*2+0];
                            stg[r*36 + cc + 1] = acc[mt][j][hh*2+1];
                        }
            }
            __syncthreads();
            {
                int r = tid >> 1, half = tid & 1;
                int ct = t0 + p2*32 + half*16;
                float bias = g_Br[blk*128 + r];
                size_t fidx = (size_t)(b*128 + r)*TLEN + ct;
                const float* oldp = g_resF[p] + fidx;
                float* newp = g_resF[1-p] + fidx;
                const float* st = stg + r*36 + half*16;
                __align__(16) float v[16];
                #pragma unroll
                for (int j = 0; j < 4; j++) {
                    float4 sv = *(const float4*)(st + j*4);
                    float4 ov = *(const float4*)(oldp + j*4);
                    v[j*4+0] = sv.x + bias + ov.x;
                    v[j*4+1] = sv.y + bias + ov.y;
                    v[j*4+2] = sv.z + bias + ov.z;
                    v[j*4+3] = sv.w + bias + ov.w;
                    *(float4*)(newp + j*4) = make_float4(v[j*4+0], v[j*4+1], v[j*4+2], v[j*4+3]);
                }
                __align__(16) bf16 hv[16], lv[16];
                #pragma unroll
                for (int j = 0; j < 16; j++) {
                    hv[j] = __float2bfloat16_rn(v[j]);
                    lv[j] = __float2bfloat16_rn(v[j] - __bfloat162float(hv[j]));
                }
                size_t rb_ = (size_t)(b*128 + r)*RSTRIDE + 128 + ct;
                bf16* dH = RPLANE(1-p,0,0) + rb_;
                bf16* dL = RPLANE(1-p,0,1) + rb_;
                ((uint4*)dH)[0] = ((uint4*)hv)[0]; ((uint4*)dH)[1] = ((uint4*)hv)[1];
                ((uint4*)dL)[0] = ((uint4*)lv)[0]; ((uint4*)dL)[1] = ((uint4*)lv)[1];
                if (!last) {
                    bf16* sH = RPLANE(1-p,1,0) + rb_ + dnext;
                    bf16* sL = RPLANE(1-p,1,1) + rb_ + dnext;
                    if ((dnext & 7) == 0) {
                        ((uint4*)sH)[0] = ((uint4*)hv)[0]; ((uint4*)sH)[1] = ((uint4*)hv)[1];
                        ((uint4*)sL)[0] = ((uint4*)lv)[0]; ((uint4*)sL)[1] = ((uint4*)lv)[1];
                    } else {
                        #pragma unroll
                        for (int j = 0; j < 16; j++) { sH[j] = hv[j]; sL[j] = lv[j]; }
                    }
                }
            }
            __syncthreads();
        }
        if (t0 == 0 && !last) {
            bf16 z = __float2bfloat16_rn(0.f);
            for (int e = tid; e < 128*dnext; e += 256) {
                int r = e / dnext, cc = e - r*dnext;
                size_t ix = (size_t)(b*128 + r)*RSTRIDE + 128 + cc;
                RPLANE(1-p,1,0)[ix] = z;
                RPLANE(1-p,1,1)[ix] = z;
            }
        }
    }
}

// ---------------- final GEMMs (R9-style, TN=128, 512 thr) ----------------
__global__ __launch_bounds__(512, 1)
void final_mma(int which, const float* __restrict__ bias, float* __restrict__ dst_ext) {
    extern __shared__ char smr[];
    uint32_t uS = smem_u32(smr);
    int tid = threadIdx.x, w = tid >> 5, lane = tid & 31;
    int mw = w >> 1, nw = w & 1;
    int rbase = mw * 32, cbase = nw * 64;
    int b = blockIdx.y, t0 = blockIdx.x * 128;
    const float* __restrict__ in = which ? g_obuf : g_skip;
    float* __restrict__ dst = which ? dst_ext : g_obuf;

    float acc[2][8][4];
    #pragma unroll
    for (int x = 0; x < 2; x++)
        #pragma unroll
        for (int y = 0; y < 8; y++)
            #pragma unroll
            for (int q = 0; q < 4; q++) acc[x][y][q] = 0.f;

    auto pff = [&](int c, int s) {
        uint32_t uSlot = uS + s*FSLOT;
        const char* ws = (const char*)g_Wf + ((size_t)which*8 + c)*40960;
        #pragma unroll
        for (int q = 0; q < 5; q++) {
            int e = tid + q*512;
            cpa16(uSlot + e*16, ws + (size_t)e*16);
        }
        #pragma unroll
        for (int q = 0; q < 2; q++) {
            int e = tid + q*512;
            int row = e >> 5, seg = e & 31;
            size_t off = ((size_t)(b*256 + c*32 + row)*TLEN + t0)*4 + seg*16;
            cpa16(uSlot + F_OFF_RAW + row*512 + seg*16, (const char*)in + off);
        }
    };

    pff(0, 0); CP_COMMIT();
    pff(1, 1); CP_COMMIT();
    #pragma unroll 1
    for (int c = 0; c < 8; c++) {
        int s = c & 1;
        CP_WAIT1(); __syncthreads();
        float* raw = (float*)(smr + s*FSLOT + F_OFF_RAW);
        bf16* Xh = (bf16*)(smr + s*FSLOT + F_OFF_X);
        bf16* Xl = (bf16*)(smr + s*FSLOT + F_OFF_X + F_XH);
        #pragma unroll
        for (int i2 = 0; i2 < 8; i2++) {
            int e = tid + i2*512;
            int t = e & 127, k = e >> 7;
            float v = fmaxf(raw[k*128 + t], 0.f);
            bf16 hv = __float2bfloat16_rn(v);
            Xh[k*136 + t] = hv;
            Xl[k*136 + t] = __float2bfloat16_rn(v - __bfloat162float(hv));
        }
        __syncthreads();
        uint32_t uW = uS + s*FSLOT;
        uint32_t uX = uW + F_OFF_X;
        mma_chunkT<2,4,272>(acc, uW, uW + W_HSTRIDE, uX, uX + F_XH, rbase, cbase, lane);
        __syncthreads();
        if (c + 2 < 8) pff(c + 2, s);
        CP_COMMIT();
    }

    float* stg = (float*)smr;
    #pragma unroll 1
    for (int p2 = 0; p2 < 2; p2++) {
        if (nw == p2) {
            #pragma unroll
            for (int mt = 0; mt < 2; mt++)
                #pragma unroll
                for (int np = 0; np < 8; np++)
                    #pragma unroll
                    for (int hh = 0; hh < 2; hh++) {
                        int r = rbase + mt*16 + (lane >> 2) + hh*8;
                        int cc = np*8 + (lane & 3)*2;
                        stg[r*68 + cc]     = acc[mt][np][hh*2+0];
                        stg[r*68 + cc + 1] = acc[mt][np][hh*2+1];
                    }
        }
        __syncthreads();
        {
            int r = tid >> 1, half = tid & 1;
            float bi = bias[r];
            float* dp = dst + ((size_t)b*256 + r)*TLEN + t0 + p2*64 + half*32;
            const float* st = stg + r*68 + half*32;
            #pragma unroll
            for (int j = 0; j < 8; j++) {
                float4 v = *(const float4*)(st + j*4);
                v.x += bi; v.y += bi; v.z += bi; v.w += bi;
                *(float4*)(dp + j*4) = v;
            }
        }
        __syncthreads();
    }
}

// ---------------- launch ----------------
extern "C" void kernel_launch(void* const* d_in, const int* in_sizes, int n_in,
                              void* d_out, int out_size) {
    const float* wav    = (const float*)d_in[0];
    const float* cond   = (const float*)d_in[1];
    const float* wav_w  = (const float*)d_in[2];
    const float* wav_b  = (const float*)d_in[3];
    const float* cond_w = (const float*)d_in[4];
    const float* cond_b = (const float*)d_in[5];
    const float* dil_w  = (const float*)d_in[6];
    const float* dil_b  = (const float*)d_in[7];
    const float* skip_w = (const float*)d_in[8];
    const float* skip_b = (const float*)d_in[9];
    const float* res_w  = (const float*)d_in[10];
    const float* res_b  = (const float*)d_in[11];
    const float* out_w  = (const float*)d_in[12];
    const float* out_b  = (const float*)d_in[13];
    const float* end_w  = (const float*)d_in[14];
    const float* end_b  = (const float*)d_in[15];

    cudaFuncSetAttribute(block_mma, cudaFuncAttributeMaxDynamicSharedMemorySize, SMEM_BLK);
    cudaFuncSetAttribute(final_mma, cudaFuncAttributeMaxDynamicSharedMemorySize, SMEM_FIN);

    size_t ntot = N1 + N2 + N3 + N4;
    pack_all<<<(int)((ntot + 255)/256), 256>>>(dil_w, cond_w, skip_w, res_w, out_w, end_w,
                                               dil_b, cond_b, skip_b, res_b);
    init_resA<<<(int)(((size_t)BATCH*128*TLEN + 255)/256), 256>>>(wav, wav_w, wav_b);
    init_cnd<<<(int)(((size_t)BATCH*96*TLEN + 255)/256), 256>>>(cond);

    dim3 gridB(TLEN / TN, BATCH);
    for (int i = 0; i < NBLK; i++) {
        int dnext = 1 << ((i + 1) % 8);
        block_mma<<<gridB, 256, SMEM_BLK>>>(i, dnext, i & 1, (i == 0) ? 1 : 0, (i == NBLK-1) ? 1 : 0);
    }
    dim3 gridF(TLEN / 128, BATCH);
    final_mma<<<gridF, 512, SMEM_FIN>>>(0, out_b, nullptr);
    final_mma<<<gridF, 512, SMEM_FIN>>>(1, end_b, (float*)d_out);
}